// round 16
// baseline (speedup 1.0000x reference)
#include <cuda_runtime.h>
#include <cuda_bf16.h>
#include <cstdint>

#define Bq 8
#define Cc 128
#define Dd 512
#define Tt 8000
#define Ll 4
#define EPSf 1e-5f
#define NBTf 64000.0f

typedef unsigned int u32;
typedef __nv_bfloat16 bf16;

// ---------------- device scratch (no allocations allowed) ----------------
__device__ float g_y1[Bq * Dd * Tt];                            // 131 MB fp32
__device__ bf16  g_hs_hi[Bq * Cc * Tt], g_hs_lo[Bq * Cc * Tt];  // 16.4 MB each
__device__ bf16  g_w1s_hi[Ll * Dd * Cc], g_w1s_lo[Ll * Dd * Cc];
__device__ bf16  g_w2s_hi[Cc * Dd], g_w2s_lo[Cc * Dd];
__device__ float g_sum[Dd], g_sumsq[Dd];
__device__ float g_scale1[Dd], g_shift1[Dd];
__device__ float g_biaseff[Cc];

// ---------------- helpers ----------------
__device__ __forceinline__ u32 smem_u32(const void* p) {
    u32 a; asm("{ .reg .u64 t; cvta.to.shared.u64 t, %1; cvt.u32.u64 %0, t; }"
               : "=r"(a) : "l"(p));
    return a;
}
__device__ __forceinline__ void split2(float v, bf16& h, bf16& l) {
    h = __float2bfloat16(v);
    l = __float2bfloat16(v - __bfloat162float(h));
}
__device__ __forceinline__ u32 pack_hi2(float v0, float v1, u32& lo_out) {
    bf16 h0, l0, h1, l1;
    split2(v0, h0, l0); split2(v1, h1, l1);
    lo_out = (u32)__bfloat16_as_ushort(l0) | ((u32)__bfloat16_as_ushort(l1) << 16);
    return (u32)__bfloat16_as_ushort(h0) | ((u32)__bfloat16_as_ushort(h1) << 16);
}

#define CPA16(dst, src) \
    asm volatile("cp.async.cg.shared.global [%0], [%1], 16;" :: "r"(dst), "l"(src))
#define CPA_COMMIT() asm volatile("cp.async.commit_group;" ::: "memory")
#define CPA_WAIT1()  asm volatile("cp.async.wait_group 1;" ::: "memory")
#define CPA_WAIT0()  asm volatile("cp.async.wait_group 0;" ::: "memory")

#define LDSM_X4(r, a) \
    asm volatile("ldmatrix.sync.aligned.m8n8.x4.shared.b16 {%0,%1,%2,%3}, [%4];" \
        : "=r"((r)[0]), "=r"((r)[1]), "=r"((r)[2]), "=r"((r)[3]) : "r"(a))
#define LDSM_X4T(r, a) \
    asm volatile("ldmatrix.sync.aligned.m8n8.x4.trans.shared.b16 {%0,%1,%2,%3}, [%4];" \
        : "=r"((r)[0]), "=r"((r)[1]), "=r"((r)[2]), "=r"((r)[3]) : "r"(a))

#define MMA16816(d, a, b0, b1) \
    asm volatile("mma.sync.aligned.m16n8k16.row.col.f32.bf16.bf16.f32 " \
        "{%0,%1,%2,%3}, {%4,%5,%6,%7}, {%8,%9}, {%0,%1,%2,%3};" \
        : "+f"((d)[0]), "+f"((d)[1]), "+f"((d)[2]), "+f"((d)[3]) \
        : "r"((a)[0]), "r"((a)[1]), "r"((a)[2]), "r"((a)[3]), "r"(b0), "r"(b1))

// gemm1 stage: A 256x(64B hi|64B lo) = 32KB, B 2 planes x 32k x 64n = 8KB -> 40KB
#define G1_STAGE 40960
#define G1_BOFF  32768
#define G1_SMEM  (2 * G1_STAGE)

// gemm2f smem: A stages 2x16KB, B tiles (single) 16KB, Y stage 32x656B
#define G2F_BT   32768
#define G2F_Y    49152
#define YROWB    656            // 160 floats + 4 pad
#define G2F_SMEM (G2F_Y + 32 * YROWB)   // 70144

// ============================================================================
// gemm1: Y[d, t0:t0+64] = prelu(W1[d,:]·H[:,t] + b1) + BN1 stats -> g_y1
// (unchanged — profiled reference kernel)
// ============================================================================
__global__ __launch_bounds__(256, 2) void gemm1_kernel(
    int layer, const float* __restrict__ bias1, const float* __restrict__ alphap)
{
    extern __shared__ __align__(1024) char smem[];
    const u32 sb = smem_u32(smem);
    const int tid = threadIdx.x;
    const int lane = tid & 31, wid = tid >> 5;
    const int wm = wid >> 1, wn = wid & 1;
    const int t0 = blockIdx.x * 64;
    const int m0 = blockIdx.y * 256;
    const int b  = blockIdx.z;

    const bf16* Ah = g_w1s_hi + (size_t)layer * Dd * Cc;
    const bf16* Al = g_w1s_lo + (size_t)layer * Dd * Cc;
    const bf16* Bh = g_hs_hi + (size_t)b * Cc * Tt;
    const bf16* Bl = g_hs_lo + (size_t)b * Cc * Tt;

    const int mb = tid >> 3, q = tid & 7;
    const u32 off0 = (u32)mb * 128 + (u32)q * 16;
    const u32 sw0  = off0 ^ ((off0 >> 3) & 0x70);
    const u32 a_dst0 = sb + sw0;
    const u32 b_dst0 = sb + G1_BOFF + sw0;
    const bf16* a_src0 = (q < 4 ? Ah : Al) + (size_t)(m0 + mb) * Cc + (q & 3) * 8;
    const size_t bso = (size_t)mb * Tt + t0 + q * 8;

    float acc[4][4][4];
#pragma unroll
    for (int i = 0; i < 4; i++)
#pragma unroll
        for (int j = 0; j < 4; j++)
#pragma unroll
            for (int r = 0; r < 4; r++) acc[i][j][r] = 0.f;

#pragma unroll
    for (int i = 0; i < 8; i++) CPA16(a_dst0 + 4096u * i, a_src0 + 4096 * i);
    CPA16(b_dst0, Bh + bso);
    CPA16(b_dst0 + 4096u, Bl + bso);
    CPA_COMMIT();

    const u32 aswx = ((u32)(lane & 7)) << 4;
    const int niter = Cc / 32;

    for (int it = 0; it < niter; it++) {
        const int stage = it & 1;
        if (it + 1 < niter) {
            const u32 so = (stage ^ 1) ? (u32)G1_STAGE : 0u;
            const int kadv = (it + 1) * 32;
#pragma unroll
            for (int i = 0; i < 8; i++)
                CPA16(a_dst0 + so + 4096u * i, a_src0 + 4096 * i + kadv);
            CPA16(b_dst0 + so, Bh + bso + (size_t)kadv * Tt);
            CPA16(b_dst0 + so + 4096u, Bl + bso + (size_t)kadv * Tt);
            CPA_COMMIT();
            CPA_WAIT1();
        } else {
            CPA_WAIT0();
        }
        __syncthreads();

        const u32 Ab  = sb + (stage ? (u32)G1_STAGE : 0u);
        const u32 Bhb = Ab + G1_BOFF;
        const u32 Blb = Bhb + 4096;

#pragma unroll
        for (int kk = 0; kk < 2; kk++) {
            u32 bhi[2][4], blo[2][4];
#pragma unroll
            for (int j = 0; j < 2; j++) {
                u32 k = (u32)(kk * 16 + ((lane >> 3) & 1) * 8 + (lane & 7));
                u32 n = (u32)(wn * 32 + j * 16 + (lane >> 4) * 8);
                u32 sw = (k * 128 + n * 2) ^ aswx;
                LDSM_X4T(bhi[j], Bhb + sw);
                LDSM_X4T(blo[j], Blb + sw);
            }
            const u32 colb = (u32)(kk * 32 + ((lane >> 4) << 4));
            {
                u32 af[4][4];
#pragma unroll
                for (int i = 0; i < 4; i++) {
                    u32 row = (u32)(wm * 64 + i * 16 + (lane & 15));
                    LDSM_X4(af[i], Ab + ((row * 128 + colb) ^ aswx));
                }
#pragma unroll
                for (int i = 0; i < 4; i++)
#pragma unroll
                    for (int jn = 0; jn < 4; jn++) {
                        const int jg = jn >> 1, jr = (jn & 1) * 2;
                        MMA16816(acc[i][jn], af[i], bhi[jg][jr], bhi[jg][jr + 1]);
                        MMA16816(acc[i][jn], af[i], blo[jg][jr], blo[jg][jr + 1]);
                    }
            }
            {
                u32 af[4][4];
#pragma unroll
                for (int i = 0; i < 4; i++) {
                    u32 row = (u32)(wm * 64 + i * 16 + (lane & 15));
                    LDSM_X4(af[i], Ab + ((row * 128 + colb + 64) ^ aswx));
                }
#pragma unroll
                for (int i = 0; i < 4; i++)
#pragma unroll
                    for (int jn = 0; jn < 4; jn++) {
                        const int jg = jn >> 1, jr = (jn & 1) * 2;
                        MMA16816(acc[i][jn], af[i], bhi[jg][jr], bhi[jg][jr + 1]);
                    }
            }
        }
        __syncthreads();
    }

    const float alpha = *alphap;
    const int colbase = t0 + wn * 32 + (lane & 3) * 2;
#pragma unroll
    for (int i = 0; i < 4; i++)
#pragma unroll
        for (int h = 0; h < 2; h++) {
            const int d = m0 + wm * 64 + i * 16 + (lane >> 2) + h * 8;
            const float bb = bias1[d];
            float s = 0.f, qq = 0.f;
            float* yp = g_y1 + ((size_t)b * Dd + d) * Tt + colbase;
#pragma unroll
            for (int jn = 0; jn < 4; jn++) {
                float v0 = acc[i][jn][h * 2] + bb;
                float v1 = acc[i][jn][h * 2 + 1] + bb;
                v0 = v0 >= 0.f ? v0 : alpha * v0;
                v1 = v1 >= 0.f ? v1 : alpha * v1;
                s += v0 + v1;
                qq += v0 * v0 + v1 * v1;
                float2 st; st.x = v0; st.y = v1;
                *(float2*)(yp + jn * 8) = st;
            }
            s += __shfl_xor_sync(0xffffffffu, s, 1);
            s += __shfl_xor_sync(0xffffffffu, s, 2);
            qq += __shfl_xor_sync(0xffffffffu, qq, 1);
            qq += __shfl_xor_sync(0xffffffffu, qq, 2);
            if ((lane & 3) == 0) {
                atomicAdd(&g_sum[d], s);
                atomicAdd(&g_sumsq[d], qq);
            }
        }
}

// ============================================================================
// gemm2f: fused dw + conv2. B tile z[k,t] recomputed on the fly from g_y1:
//   u = in-range ? y1*scale1 + shift1 : 0   (zero-pad AFTER BN, as reference)
//   z = prelu(bd + w0*u[t-dil] + w1*u[t] + w2*u[t+dil])  -> split bf16 tiles
// Then O[c, t0:t0+128] = W2s[c,:]·z + biaseff (+x -> out | split -> h).
// FIX vs R13: pass-B tile stores use GENERIC pointers (smem + off), not the
// cvta.to.shared 32-bit address (generic deref of shared-window addr = fault).
// ============================================================================
__global__ __launch_bounds__(256, 2) void gemm2f_kernel(
    int last, int dil,
    const float* __restrict__ wd, const float* __restrict__ bd,
    const float* __restrict__ a2p,
    const float* __restrict__ Xres, float* __restrict__ OutF)
{
    extern __shared__ __align__(1024) char smem[];
    const u32 sb = smem_u32(smem);
    const int tid = threadIdx.x;
    const int lane = tid & 31, wid = tid >> 5;
    const int wm = wid >> 2, wn = wid & 3;       // warp grid 2 x 4
    int t0 = blockIdx.x * 128;
    if (t0 > Tt - 128) t0 = Tt - 128;
    const int b = blockIdx.z;

    if (blockIdx.x == 0 && blockIdx.z == 0) {    // stats reset for next layer
        for (int i = tid; i < Dd; i += 256) { g_sum[i] = 0.f; g_sumsq[i] = 0.f; }
    }

    const float alpha = *a2p;
    const float* Yg = g_y1 + (size_t)b * Dd * Tt;

    // ---- A staging ----
    const int mb = tid >> 3, q = tid & 7;
    const u32 off0 = (u32)mb * 128 + (u32)q * 16;
    const u32 sw0  = off0 ^ ((off0 >> 3) & 0x70);
    const u32 a_dst0 = sb + sw0;
    const bf16* a_src0 = (q < 4 ? g_w2s_hi : g_w2s_lo) + (size_t)mb * Dd + (q & 3) * 8;

    // ---- Y staging: 32 rows x 40 chunks = 1280, 5 per thread ----
    u32 y_dst[5]; int y_r[5], y_c[5];
#pragma unroll
    for (int i = 0; i < 5; i++) {
        int cid = tid + i * 256;
        y_r[i] = cid / 40;
        int c = cid % 40;
        y_c[i] = t0 - 16 + c * 4;                      // global col of chunk
        y_dst[i] = sb + G2F_Y + (u32)y_r[i] * YROWB + (u32)c * 16;
    }

    float acc[4][4][4];
#pragma unroll
    for (int i = 0; i < 4; i++)
#pragma unroll
        for (int j = 0; j < 4; j++)
#pragma unroll
            for (int r = 0; r < 4; r++) acc[i][j][r] = 0.f;

    // prologue: A(0) + Y(0)
#pragma unroll
    for (int i = 0; i < 4; i++) CPA16(a_dst0 + 4096u * i, a_src0 + 16384 * i);
#pragma unroll
    for (int i = 0; i < 5; i++)
        if (y_c[i] >= 0 && y_c[i] <= Tt - 4)
            CPA16(y_dst[i], Yg + (size_t)y_r[i] * Tt + y_c[i]);
    CPA_COMMIT();

    const u32 aswx = ((u32)(lane & 7)) << 4;
    const int tr = tid >> 3, seg = tid & 7;      // transform row / segment

    for (int kc = 0; kc < 16; kc++) {
        CPA_WAIT0();
        __syncthreads();                          // Y(kc), A(kc) resident

        const int d = kc * 32 + tr;
        float* Yrow = (float*)(smem + G2F_Y + tr * YROWB);

        // pass A: BN1-apply in place with zero-pad guard
        {
            const float sc = g_scale1[d], sh = g_shift1[d];
#pragma unroll
            for (int e = 0; e < 20; e++) {
                const int col = seg * 20 + e;
                const int tg = t0 - 16 + col;
                float v = Yrow[col];
                Yrow[col] = (tg >= 0 && tg < Tt) ? v * sc + sh : 0.f;
            }
        }
        __syncthreads();

        // pass B: depthwise conv + prelu + split -> B tiles (swizzled)
        {
            const float w0 = wd[d * 3 + 0], w1 = wd[d * 3 + 1], w2v = wd[d * 3 + 2];
            const float bb = bd[d];
            const float* u = Yrow + 16;
            u32 hibuf[8], lobuf[8];
#pragma unroll
            for (int jj = 0; jj < 16; jj += 2) {
                const int j = seg * 16 + jj;
                float z0 = bb + w0 * u[j - dil]     + w1 * u[j]     + w2v * u[j + dil];
                float z1 = bb + w0 * u[j + 1 - dil] + w1 * u[j + 1] + w2v * u[j + 1 + dil];
                z0 = z0 >= 0.f ? z0 : alpha * z0;
                z1 = z1 >= 0.f ? z1 : alpha * z1;
                hibuf[jj >> 1] = pack_hi2(z0, z1, lobuf[jj >> 1]);
            }
            const int nb = seg >> 2;              // (seg*16)>>6
            char* pg = smem + G2F_BT + nb * 4096; // GENERIC pointer (the fix)
#pragma unroll
            for (int w = 0; w < 8; w++) {
                const int col64 = (seg * 16 + w * 2) & 63;
                u32 off = (u32)tr * 128 + (u32)col64 * 2;
                u32 sw = off ^ ((off >> 3) & 0x70);
                *(u32*)(pg + sw) = hibuf[w];
                *(u32*)(pg + 8192 + sw) = lobuf[w];
            }
        }
        __syncthreads();                          // tiles visible; Y free

        if (kc + 1 < 16) {                        // refill while MMA runs
            const u32 aso = (u32)((kc + 1) & 1) * 16384u;
            const int kadv = (kc + 1) * 32;
#pragma unroll
            for (int i = 0; i < 4; i++)
                CPA16(a_dst0 + aso + 4096u * i, a_src0 + 16384 * i + kadv);
#pragma unroll
            for (int i = 0; i < 5; i++)
                if (y_c[i] >= 0 && y_c[i] <= Tt - 4)
                    CPA16(y_dst[i], Yg + (size_t)(kadv + y_r[i]) * Tt + y_c[i]);
        }
        CPA_COMMIT();

        // ---- MMA on tiles(kc) + A(kc) ----
        const u32 Ab  = sb + (u32)(kc & 1) * 16384u;
        const u32 nb4 = (u32)(wn >> 1) * 4096u;
        const u32 Bhb = sb + G2F_BT + nb4;
        const u32 Blb = sb + G2F_BT + 8192u + nb4;

#pragma unroll
        for (int kk = 0; kk < 2; kk++) {
            u32 bhi[2][4], blo[2][4];
#pragma unroll
            for (int j = 0; j < 2; j++) {
                u32 k = (u32)(kk * 16 + ((lane >> 3) & 1) * 8 + (lane & 7));
                u32 n = (u32)((wn & 1) * 32 + j * 16 + (lane >> 4) * 8);
                u32 sw = (k * 128 + n * 2) ^ aswx;
                LDSM_X4T(bhi[j], Bhb + sw);
                LDSM_X4T(blo[j], Blb + sw);
            }
            const u32 colb = (u32)(kk * 32 + ((lane >> 4) << 4));
            {
                u32 af[4][4];
#pragma unroll
                for (int i = 0; i < 4; i++) {
                    u32 row = (u32)(wm * 64 + i * 16 + (lane & 15));
                    LDSM_X4(af[i], Ab + ((row * 128 + colb) ^ aswx));
                }
#pragma unroll
                for (int i = 0; i < 4; i++)
#pragma unroll
                    for (int jn = 0; jn < 4; jn++) {
                        const int jg = jn >> 1, jr = (jn & 1) * 2;
                        MMA16816(acc[i][jn], af[i], bhi[jg][jr], bhi[jg][jr + 1]);
                        MMA16816(acc[i][jn], af[i], blo[jg][jr], blo[jg][jr + 1]);
                    }
            }
            {
                u32 af[4][4];
#pragma unroll
                for (int i = 0; i < 4; i++) {
                    u32 row = (u32)(wm * 64 + i * 16 + (lane & 15));
                    LDSM_X4(af[i], Ab + ((row * 128 + colb + 64) ^ aswx));
                }
#pragma unroll
                for (int i = 0; i < 4; i++)
#pragma unroll
                    for (int jn = 0; jn < 4; jn++) {
                        const int jg = jn >> 1, jr = (jn & 1) * 2;
                        MMA16816(acc[i][jn], af[i], bhi[jg][jr], bhi[jg][jr + 1]);
                    }
            }
        }
    }

    // ---- epilogue ----
    const int colbase = t0 + wn * 32 + (lane & 3) * 2;
#pragma unroll
    for (int i = 0; i < 4; i++)
#pragma unroll
        for (int h = 0; h < 2; h++) {
            const int c = wm * 64 + i * 16 + (lane >> 2) + h * 8;
            const float bb = g_biaseff[c];
            if (last) {
                float* op = OutF + ((size_t)b * Cc + c) * Tt + colbase;
                const float* xp = Xres + ((size_t)b * Cc + c) * Tt + colbase;
#pragma unroll
                for (int jn = 0; jn < 4; jn++) {
                    float2 xv = *(const float2*)(xp + jn * 8);
                    float2 st;
                    st.x = acc[i][jn][h * 2] + bb + xv.x;
                    st.y = acc[i][jn][h * 2 + 1] + bb + xv.y;
                    *(float2*)(op + jn * 8) = st;
                }
            } else {
                u32* hp = (u32*)(g_hs_hi + ((size_t)b * Cc + c) * Tt + colbase);
                u32* lp = (u32*)(g_hs_lo + ((size_t)b * Cc + c) * Tt + colbase);
#pragma unroll
                for (int jn = 0; jn < 4; jn++) {
                    float v0 = acc[i][jn][h * 2] + bb;
                    float v1 = acc[i][jn][h * 2 + 1] + bb;
                    u32 lw, hw = pack_hi2(v0, v1, lw);
                    hp[jn * 4] = hw;
                    lp[jn * 4] = lw;
                }
            }
        }
}

// ============================================================================
// finalize1: BN1 params from stats, reset accumulators.
// ============================================================================
__global__ void finalize1_kernel(const float* __restrict__ gamma,
                                 const float* __restrict__ beta)
{
    int d = threadIdx.x;
    float mean = g_sum[d] * (1.f / NBTf);
    float var  = g_sumsq[d] * (1.f / NBTf) - mean * mean;
    float sc = gamma[d] * rsqrtf(var + EPSf);
    g_scale1[d] = sc;
    g_shift1[d] = beta[d] - mean * sc;
    g_sum[d] = 0.f;
    g_sumsq[d] = 0.f;
}

// ============================================================================
// dw_stats: BN1-apply + dilated depthwise + PReLU, STATS ONLY (no z write).
// ============================================================================
__global__ __launch_bounds__(256) void dw_stats_kernel(
    const float* __restrict__ wd, const float* __restrict__ bd,
    const float* __restrict__ a2p, int dil)
{
    __shared__ float s_in[1024];
    const int d = blockIdx.y, b = blockIdx.z;
    const int tstart = blockIdx.x * 1000;
    const size_t base = ((size_t)b * Dd + d) * Tt;
    const float* in = g_y1 + base;
    const int tid = threadIdx.x;

    {
        const int g = tstart - 16 + tid * 4;
        float4 v;
        if (g >= 0 && g + 3 < Tt) {
            v = *(const float4*)(in + g);
        } else {
            v.x = (g + 0 >= 0 && g + 0 < Tt) ? in[g + 0] : 0.f;
            v.y = (g + 1 >= 0 && g + 1 < Tt) ? in[g + 1] : 0.f;
            v.z = (g + 2 >= 0 && g + 2 < Tt) ? in[g + 2] : 0.f;
            v.w = (g + 3 >= 0 && g + 3 < Tt) ? in[g + 3] : 0.f;
        }
        *(float4*)(s_in + tid * 4) = v;
    }
    __syncthreads();

    const float w0 = wd[d * 3 + 0], w1 = wd[d * 3 + 1], w2v = wd[d * 3 + 2];
    const float sc = g_scale1[d], sh = g_shift1[d];
    const float bias = bd[d], alpha = *a2p;

    float ls = 0.f, lq = 0.f;
    if (tid < 250) {
        const int t = tstart + tid * 4;
        const int li = tid * 4 + 16;
#pragma unroll
        for (int e = 0; e < 4; e++) {
            const int tt = t + e;
            float acc = bias;
            if (tt - dil >= 0) acc += w0  * (s_in[li + e - dil] * sc + sh);
            acc                     += w1  * (s_in[li + e]       * sc + sh);
            if (tt + dil < Tt) acc += w2v * (s_in[li + e + dil] * sc + sh);
            float v = acc >= 0.f ? acc : alpha * acc;
            ls += v; lq += v * v;
        }
    }
#pragma unroll
    for (int off = 16; off >= 1; off >>= 1) {
        ls += __shfl_xor_sync(0xffffffffu, ls, off);
        lq += __shfl_xor_sync(0xffffffffu, lq, off);
    }
    __shared__ float ss[8], sq[8];
    int wi = tid >> 5, lane = tid & 31;
    if (lane == 0) { ss[wi] = ls; sq[wi] = lq; }
    __syncthreads();
    if (tid == 0) {
        float S = 0.f, Q = 0.f;
#pragma unroll
        for (int w = 0; w < 8; w++) { S += ss[w]; Q += sq[w]; }
        atomicAdd(&g_sum[d], S);
        atomicAdd(&g_sumsq[d], Q);
    }
}

// ============================================================================
// convert_w2: BN2 params inline + W2*scale2 -> bf16 splits + effective bias.
// ============================================================================
__global__ __launch_bounds__(256) void convert_w2_kernel(
    const float* __restrict__ w2, const float* __restrict__ b2,
    const float* __restrict__ gamma, const float* __restrict__ beta)
{
    const int c = blockIdx.x;
    float local = 0.f;
    for (int d = threadIdx.x; d < Dd; d += 256) {
        float mean = g_sum[d] * (1.f / NBTf);
        float var  = g_sumsq[d] * (1.f / NBTf) - mean * mean;
        float scv = gamma[d] * rsqrtf(var + EPSf);
        float shv = beta[d] - mean * scv;
        float w = w2[(size_t)c * Dd + d];
        bf16 h, l;
        split2(w * scv, h, l);
        g_w2s_hi[(size_t)c * Dd + d] = h;
        g_w2s_lo[(size_t)c * Dd + d] = l;
        local += w * shv;
    }
#pragma unroll
    for (int off = 16; off >= 1; off >>= 1)
        local += __shfl_xor_sync(0xffffffffu, local, off);
    __shared__ float sred[8];
    int wi = threadIdx.x >> 5, lane = threadIdx.x & 31;
    if (lane == 0) sred[wi] = local;
    __syncthreads();
    if (threadIdx.x == 0) {
        float tot = 0.f;
#pragma unroll
        for (int w = 0; w < 8; w++) tot += sred[w];
        g_biaseff[c] = b2[c] + tot;
    }
}

// ============================================================================
// converters + reset (reset keeps gemm1 at profiled launch slot #4).
// ============================================================================
__global__ void convert_x_kernel(const float* __restrict__ x)
{
    int p = blockIdx.x * 256 + threadIdx.x;
    if (p < Bq * Cc * Tt / 2) {
        float2 v = ((const float2*)x)[p];
        u32 lw, hw = pack_hi2(v.x, v.y, lw);
        ((u32*)g_hs_hi)[p] = hw;
        ((u32*)g_hs_lo)[p] = lw;
    }
}
__global__ void convert_w1_kernel(const float* __restrict__ w1)
{
    int i = blockIdx.x * 256 + threadIdx.x;
    if (i < Ll * Dd * Cc) {
        bf16 h, l;
        split2(w1[i], h, l);
        g_w1s_hi[i] = h;
        g_w1s_lo[i] = l;
    }
}
__global__ void reset_kernel()
{
    int d = threadIdx.x;
    g_sum[d] = 0.f;
    g_sumsq[d] = 0.f;
}

// ============================================================================
// Host driver — graph-capturable: 23 kernel launches, no sync, no allocs.
// ============================================================================
extern "C" void kernel_launch(void* const* d_in, const int* in_sizes, int n_in,
                              void* d_out, int out_size)
{
    const float* x   = (const float*)d_in[0];
    const float* w1  = (const float*)d_in[1];
    const float* b1  = (const float*)d_in[2];
    const float* a1  = (const float*)d_in[3];
    const float* g1  = (const float*)d_in[4];
    const float* be1 = (const float*)d_in[5];
    const float* wd  = (const float*)d_in[6];
    const float* bd  = (const float*)d_in[7];
    const float* a2  = (const float*)d_in[8];
    const float* g2  = (const float*)d_in[9];
    const float* be2 = (const float*)d_in[10];
    const float* w2  = (const float*)d_in[11];
    const float* b2  = (const float*)d_in[12];
    float* out = (float*)d_out;

    cudaFuncSetAttribute(gemm1_kernel,
                         cudaFuncAttributeMaxDynamicSharedMemorySize, G1_SMEM);
    cudaFuncSetAttribute(gemm2f_kernel,
                         cudaFuncAttributeMaxDynamicSharedMemorySize, G2F_SMEM);

    convert_x_kernel<<<(Bq * Cc * Tt / 2 + 255) / 256, 256>>>(x);     // #1
    convert_w1_kernel<<<(Ll * Dd * Cc + 255) / 256, 256>>>(w1);       // #2
    reset_kernel<<<1, 512>>>();                                       // #3

    dim3 gg1(125, 2, 8);   // 64-t tiles, 256-m tiles, batch
    dim3 gg2(63, 1, 8);    // 128-t tiles (last clamped), 1, batch
    dim3 gdw(8, 512, 8);

    for (int l = 0; l < Ll; l++) {
        gemm1_kernel<<<gg1, 256, G1_SMEM>>>(l, b1 + l * Dd, a1 + l);  // #4 profiled
        finalize1_kernel<<<1, 512>>>(g1 + l * Dd, be1 + l * Dd);
        dw_stats_kernel<<<gdw, 256>>>(wd + l * Dd * 3, bd + l * Dd, a2 + l, 1 << l);
        convert_w2_kernel<<<128, 256>>>(w2 + l * Cc * Dd, b2 + l * Cc,
                                        g2 + l * Dd, be2 + l * Dd);
        gemm2f_kernel<<<gg2, 256, G2F_SMEM>>>(l == Ll - 1 ? 1 : 0, 1 << l,
                                              wd + l * Dd * 3, bd + l * Dd,
                                              a2 + l, x, out);
    }
}

// round 17
// speedup vs baseline: 1.3162x; 1.3162x over previous
#include <cuda_runtime.h>
#include <cuda_bf16.h>
#include <cstdint>

#define Bq 8
#define Cc 128
#define Dd 512
#define Tt 8000
#define Ll 4
#define EPSf 1e-5f
#define NBTf 64000.0f

typedef unsigned int u32;
typedef __nv_bfloat16 bf16;

// ---------------- device scratch (no allocations allowed) ----------------
__device__ float g_y1[Bq * Dd * Tt];                            // 131 MB fp32
__device__ bf16  g_zs_hi[Bq * Dd * Tt], g_zs_lo[Bq * Dd * Tt];  // 65.5 MB each
__device__ bf16  g_hs_hi[Bq * Cc * Tt], g_hs_lo[Bq * Cc * Tt];  // 16.4 MB each
__device__ bf16  g_w1s_hi[Ll * Dd * Cc], g_w1s_lo[Ll * Dd * Cc];
__device__ bf16  g_w2s_hi[Cc * Dd], g_w2s_lo[Cc * Dd];
__device__ float g_sum[Dd], g_sumsq[Dd];
__device__ float g_scale1[Dd], g_shift1[Dd];
__device__ float g_scale2[Dd], g_shift2[Dd];
__device__ float g_biaseff[Cc];

// ---------------- helpers ----------------
__device__ __forceinline__ u32 smem_u32(const void* p) {
    u32 a; asm("{ .reg .u64 t; cvta.to.shared.u64 t, %1; cvt.u32.u64 %0, t; }"
               : "=r"(a) : "l"(p));
    return a;
}
__device__ __forceinline__ void split2(float v, bf16& h, bf16& l) {
    h = __float2bfloat16(v);
    l = __float2bfloat16(v - __bfloat162float(h));
}
__device__ __forceinline__ u32 pack_hi2(float v0, float v1, u32& lo_out) {
    bf16 h0, l0, h1, l1;
    split2(v0, h0, l0); split2(v1, h1, l1);
    lo_out = (u32)__bfloat16_as_ushort(l0) | ((u32)__bfloat16_as_ushort(l1) << 16);
    return (u32)__bfloat16_as_ushort(h0) | ((u32)__bfloat16_as_ushort(h1) << 16);
}

#define CPA16(dst, src) \
    asm volatile("cp.async.cg.shared.global [%0], [%1], 16;" :: "r"(dst), "l"(src))
#define CPA_COMMIT() asm volatile("cp.async.commit_group;" ::: "memory")
#define CPA_WAIT1()  asm volatile("cp.async.wait_group 1;" ::: "memory")
#define CPA_WAIT0()  asm volatile("cp.async.wait_group 0;" ::: "memory")

#define LDSM_X4(r, a) \
    asm volatile("ldmatrix.sync.aligned.m8n8.x4.shared.b16 {%0,%1,%2,%3}, [%4];" \
        : "=r"((r)[0]), "=r"((r)[1]), "=r"((r)[2]), "=r"((r)[3]) : "r"(a))
#define LDSM_X4T(r, a) \
    asm volatile("ldmatrix.sync.aligned.m8n8.x4.trans.shared.b16 {%0,%1,%2,%3}, [%4];" \
        : "=r"((r)[0]), "=r"((r)[1]), "=r"((r)[2]), "=r"((r)[3]) : "r"(a))

#define MMA16816(d, a, b0, b1) \
    asm volatile("mma.sync.aligned.m16n8k16.row.col.f32.bf16.bf16.f32 " \
        "{%0,%1,%2,%3}, {%4,%5,%6,%7}, {%8,%9}, {%0,%1,%2,%3};" \
        : "+f"((d)[0]), "+f"((d)[1]), "+f"((d)[2]), "+f"((d)[3]) \
        : "r"((a)[0]), "r"((a)[1]), "r"((a)[2]), "r"((a)[3]), "r"(b0), "r"(b1))

// smem stage: A(hi|lo packed, 128 rows x 128B) 16KB, Bhi 4KB, Blo 4KB = 24KB
#define STAGE_BYTES 24576
#define B_OFF       16384

// ============================================================================
// GEMM: C[m, t0:t0+64] = sum_k A[m,k] * B[k,t]  via bf16 split, 3-pass mma.sync
// (exact R7 / 965us structure: 2-stage cp.async, 2 syncs per k-iter)
// mode 0: conv1  A = w1 splits (K=128), B = h splits; epi: bias+prelu+stats -> g_y1
// mode 1: conv2  A = w2*scale2 splits (K=512), B = z splits;
//                epi: biaseff (+x -> out on last, else split -> h)
// ============================================================================
__global__ __launch_bounds__(256) void gemm_tc_kernel(
    int mode, int last, int layer,
    const float* __restrict__ bias1, const float* __restrict__ alphap,
    const float* __restrict__ Xres, float* __restrict__ OutF)
{
    __shared__ __align__(1024) char smem[2 * STAGE_BYTES];
    const u32 sb = smem_u32(smem);
    const int tid = threadIdx.x;
    const int lane = tid & 31, wid = tid >> 5;
    const int wm = wid >> 1, wn = wid & 1;       // warp grid 4 x 2
    const int t0 = blockIdx.x * 64;
    const int m0 = blockIdx.y * 128;
    const int b  = blockIdx.z;

    const bf16 *Ah, *Al, *Bh, *Bl;
    int K;
    if (mode == 0) {
        Ah = g_w1s_hi + (size_t)layer * Dd * Cc;
        Al = g_w1s_lo + (size_t)layer * Dd * Cc;
        Bh = g_hs_hi + (size_t)b * Cc * Tt;
        Bl = g_hs_lo + (size_t)b * Cc * Tt;
        K = Cc;
    } else {
        Ah = g_w2s_hi; Al = g_w2s_lo;
        Bh = g_zs_hi + (size_t)b * Dd * Tt;
        Bl = g_zs_lo + (size_t)b * Dd * Tt;
        K = Dd;
    }
    const int niter = K / 32;

    // A: 128 rows x 8 chunks/row (cols 0-3 = hi k0..31, cols 4-7 = lo) -> 4/thread
    u32 a_dst[4]; const bf16* a_src[4];
#pragma unroll
    for (int i = 0; i < 4; i++) {
        int c = tid + i * 256;
        int m = c >> 3, q = c & 7;
        u32 off = (u32)m * 128 + (u32)q * 16;
        a_dst[i] = sb + (off ^ ((off >> 3) & 0x70));
        a_src[i] = (q < 4 ? Ah : Al) + (size_t)(m0 + m) * K + (q & 3) * 8;
    }
    // B: 2 planes x 32 k-rows x 8 chunks/row = 512 chunks -> 2/thread
    u32 b_dst[2]; const bf16* b_src[2];
#pragma unroll
    for (int i = 0; i < 2; i++) {
        int c = tid + i * 256;
        int plane = c >> 8, k = (c >> 3) & 31, q = c & 7;
        u32 off = (u32)k * 128 + (u32)q * 16;
        b_dst[i] = sb + B_OFF + (u32)plane * 4096 + (off ^ ((off >> 3) & 0x70));
        b_src[i] = (plane ? Bl : Bh) + (size_t)k * Tt + t0 + q * 8;
    }

    float acc[2][4][4];
#pragma unroll
    for (int i = 0; i < 2; i++)
#pragma unroll
        for (int j = 0; j < 4; j++)
#pragma unroll
            for (int r = 0; r < 4; r++) acc[i][j][r] = 0.f;

    // prologue: stage 0
#pragma unroll
    for (int i = 0; i < 4; i++) CPA16(a_dst[i], a_src[i]);
#pragma unroll
    for (int i = 0; i < 2; i++) CPA16(b_dst[i], b_src[i]);
    CPA_COMMIT();

    const u32 aswx = ((u32)(lane & 7)) << 4;

    for (int it = 0; it < niter; it++) {
        const int stage = it & 1;
        if (it + 1 < niter) {
            const u32 so = (stage ^ 1) ? STAGE_BYTES : 0;
            const int kadv = (it + 1) * 32;
#pragma unroll
            for (int i = 0; i < 4; i++) CPA16(a_dst[i] + so, a_src[i] + kadv);
#pragma unroll
            for (int i = 0; i < 2; i++)
                CPA16(b_dst[i] + so, b_src[i] + (size_t)kadv * Tt);
            CPA_COMMIT();
            CPA_WAIT1();
        } else {
            CPA_WAIT0();
        }
        __syncthreads();

        const u32 Abase  = sb + (stage ? STAGE_BYTES : 0);
        const u32 Bhbase = Abase + B_OFF;
        const u32 Blbase = Bhbase + 4096;

#pragma unroll
        for (int kk = 0; kk < 2; kk++) {
            u32 ahi[2][4], alo[2][4], bhi[2][4], blo[2][4];
#pragma unroll
            for (int i = 0; i < 2; i++) {
                u32 row = (u32)(wm * 32 + i * 16 + (lane & 15));
                u32 colb = (u32)(kk * 32 + ((lane >> 4) << 4));
                u32 offh = row * 128 + colb;
                LDSM_X4(ahi[i], Abase + (offh ^ aswx));
                LDSM_X4(alo[i], Abase + ((offh + 64) ^ aswx));
            }
#pragma unroll
            for (int j = 0; j < 2; j++) {
                u32 k = (u32)(kk * 16 + ((lane >> 3) & 1) * 8 + (lane & 7));
                u32 n = (u32)(wn * 32 + j * 16 + (lane >> 4) * 8);
                u32 off = k * 128 + n * 2;
                u32 sw = off ^ aswx;
                LDSM_X4T(bhi[j], Bhbase + sw);
                LDSM_X4T(blo[j], Blbase + sw);
            }
#pragma unroll
            for (int i = 0; i < 2; i++) {
#pragma unroll
                for (int jn = 0; jn < 4; jn++) {
                    const int jg = jn >> 1, jr = (jn & 1) * 2;
                    MMA16816(acc[i][jn], ahi[i], bhi[jg][jr], bhi[jg][jr + 1]);
                    MMA16816(acc[i][jn], ahi[i], blo[jg][jr], blo[jg][jr + 1]);
                    MMA16816(acc[i][jn], alo[i], bhi[jg][jr], bhi[jg][jr + 1]);
                }
            }
        }
        __syncthreads();
    }

    // ---- epilogue ----
    const int colbase = t0 + wn * 32 + (lane & 3) * 2;
    if (mode == 0) {
        const float alpha = *alphap;
#pragma unroll
        for (int i = 0; i < 2; i++)
#pragma unroll
            for (int h = 0; h < 2; h++) {
                const int d = m0 + wm * 32 + i * 16 + (lane >> 2) + h * 8;
                const float bb = bias1[d];
                float s = 0.f, q = 0.f;
                float* yp = g_y1 + ((size_t)b * Dd + d) * Tt + colbase;
#pragma unroll
                for (int jn = 0; jn < 4; jn++) {
                    float v0 = acc[i][jn][h * 2] + bb;
                    float v1 = acc[i][jn][h * 2 + 1] + bb;
                    v0 = v0 >= 0.f ? v0 : alpha * v0;
                    v1 = v1 >= 0.f ? v1 : alpha * v1;
                    s += v0 + v1;
                    q += v0 * v0 + v1 * v1;
                    float2 st; st.x = v0; st.y = v1;
                    *(float2*)(yp + jn * 8) = st;
                }
                s += __shfl_xor_sync(0xffffffffu, s, 1);
                s += __shfl_xor_sync(0xffffffffu, s, 2);
                q += __shfl_xor_sync(0xffffffffu, q, 1);
                q += __shfl_xor_sync(0xffffffffu, q, 2);
                if ((lane & 3) == 0) {
                    atomicAdd(&g_sum[d], s);
                    atomicAdd(&g_sumsq[d], q);
                }
            }
    } else {
#pragma unroll
        for (int i = 0; i < 2; i++)
#pragma unroll
            for (int h = 0; h < 2; h++) {
                const int c = wm * 32 + i * 16 + (lane >> 2) + h * 8;
                const float bb = g_biaseff[c];
                if (last) {
                    float* op = OutF + ((size_t)b * Cc + c) * Tt + colbase;
                    const float* xp = Xres + ((size_t)b * Cc + c) * Tt + colbase;
#pragma unroll
                    for (int jn = 0; jn < 4; jn++) {
                        float2 xv = *(const float2*)(xp + jn * 8);
                        float2 st;
                        st.x = acc[i][jn][h * 2] + bb + xv.x;
                        st.y = acc[i][jn][h * 2 + 1] + bb + xv.y;
                        *(float2*)(op + jn * 8) = st;
                    }
                } else {
                    u32* hp = (u32*)(g_hs_hi + ((size_t)b * Cc + c) * Tt + colbase);
                    u32* lp = (u32*)(g_hs_lo + ((size_t)b * Cc + c) * Tt + colbase);
#pragma unroll
                    for (int jn = 0; jn < 4; jn++) {
                        float v0 = acc[i][jn][h * 2] + bb;
                        float v1 = acc[i][jn][h * 2 + 1] + bb;
                        u32 lw, hw = pack_hi2(v0, v1, lw);
                        hp[jn * 4] = hw;
                        lp[jn * 4] = lw;
                    }
                }
            }
    }
}

// ============================================================================
// finalize1: BN1 params from stats, reset accumulators.
// ============================================================================
__global__ void finalize1_kernel(const float* __restrict__ gamma,
                                 const float* __restrict__ beta)
{
    int d = threadIdx.x;
    float mean = g_sum[d] * (1.f / NBTf);
    float var  = g_sumsq[d] * (1.f / NBTf) - mean * mean;
    float sc = gamma[d] * rsqrtf(var + EPSf);
    g_scale1[d] = sc;
    g_shift1[d] = beta[d] - mean * sc;
    g_sum[d] = 0.f;
    g_sumsq[d] = 0.f;
}

// ============================================================================
// dw: BN1-apply + dilated depthwise K=3 + PReLU + BN2 stats; z -> hi/lo bf16.
// (exact R7 version; now at profiled launch slot #4)
// ============================================================================
__global__ __launch_bounds__(256) void dw_kernel(
    const float* __restrict__ wd, const float* __restrict__ bd,
    const float* __restrict__ a2p, int dil)
{
    const int d = blockIdx.y, b = blockIdx.z;
    const int tstart = blockIdx.x * 1000;
    const size_t base = ((size_t)b * Dd + d) * Tt;
    const float* in = g_y1 + base;
    const float w0 = wd[d * 3 + 0], w1 = wd[d * 3 + 1], w2v = wd[d * 3 + 2];
    const float sc = g_scale1[d], sh = g_shift1[d];
    const float bias = bd[d], alpha = *a2p;

    float ls = 0.f, lq = 0.f;
    for (int p = threadIdx.x; p < 500; p += 256) {
        const int t = tstart + 2 * p;
        float v[2];
#pragma unroll
        for (int e = 0; e < 2; e++) {
            const int tt = t + e;
            float acc = bias;
            int tm = tt - dil, tp = tt + dil;
            if (tm >= 0) acc += w0  * (in[tm] * sc + sh);
            acc           += w1  * (in[tt] * sc + sh);
            if (tp < Tt) acc += w2v * (in[tp] * sc + sh);
            v[e] = acc >= 0.f ? acc : alpha * acc;
            ls += v[e]; lq += v[e] * v[e];
        }
        u32 lw, hw = pack_hi2(v[0], v[1], lw);
        *(u32*)(g_zs_hi + base + t) = hw;
        *(u32*)(g_zs_lo + base + t) = lw;
    }
#pragma unroll
    for (int off = 16; off >= 1; off >>= 1) {
        ls += __shfl_xor_sync(0xffffffffu, ls, off);
        lq += __shfl_xor_sync(0xffffffffu, lq, off);
    }
    __shared__ float ss[8], sq[8];
    int wi = threadIdx.x >> 5, lane = threadIdx.x & 31;
    if (lane == 0) { ss[wi] = ls; sq[wi] = lq; }
    __syncthreads();
    if (threadIdx.x == 0) {
        float S = 0.f, Q = 0.f;
#pragma unroll
        for (int w = 0; w < 8; w++) { S += ss[w]; Q += sq[w]; }
        atomicAdd(&g_sum[d], S);
        atomicAdd(&g_sumsq[d], Q);
    }
}

// ============================================================================
// finalize2a: BN2 params, reset accumulators.
// ============================================================================
__global__ void finalize2a_kernel(const float* __restrict__ gamma,
                                  const float* __restrict__ beta)
{
    int d = threadIdx.x;
    float mean = g_sum[d] * (1.f / NBTf);
    float var  = g_sumsq[d] * (1.f / NBTf) - mean * mean;
    float sc = gamma[d] * rsqrtf(var + EPSf);
    g_scale2[d] = sc;
    g_shift2[d] = beta[d] - mean * sc;
    g_sum[d] = 0.f;
    g_sumsq[d] = 0.f;
}

// ============================================================================
// convert_w2: W2*scale2 -> bf16 splits + effective bias (parallel dot).
// ============================================================================
__global__ __launch_bounds__(256) void convert_w2_kernel(
    const float* __restrict__ w2, const float* __restrict__ b2)
{
    const int c = blockIdx.x;
    float local = 0.f;
    for (int d = threadIdx.x; d < Dd; d += 256) {
        float w = w2[(size_t)c * Dd + d];
        bf16 h, l;
        split2(w * g_scale2[d], h, l);
        g_w2s_hi[(size_t)c * Dd + d] = h;
        g_w2s_lo[(size_t)c * Dd + d] = l;
        local += w * g_shift2[d];
    }
#pragma unroll
    for (int off = 16; off >= 1; off >>= 1)
        local += __shfl_xor_sync(0xffffffffu, local, off);
    __shared__ float sred[8];
    int wi = threadIdx.x >> 5, lane = threadIdx.x & 31;
    if (lane == 0) sred[wi] = local;
    __syncthreads();
    if (threadIdx.x == 0) {
        float tot = 0.f;
#pragma unroll
        for (int w = 0; w < 8; w++) tot += sred[w];
        g_biaseff[c] = b2[c] + tot;
    }
}

// ============================================================================
// prep: merged convert_x + convert_w1 + stats reset (one launch -> dw is #4).
// blocks [0, NXB): x pairs; blocks [NXB, NXB+NWB): w1 elems; block 0: reset.
// ============================================================================
#define NXB 16000    // (Bq*Cc*Tt/2) / 256
#define NWB 1024     // (Ll*Dd*Cc) / 256
__global__ void prep_kernel(const float* __restrict__ x,
                            const float* __restrict__ w1)
{
    const int bx = blockIdx.x;
    if (bx == 0) {
        g_sum[threadIdx.x] = 0.f;       g_sumsq[threadIdx.x] = 0.f;
        g_sum[threadIdx.x + 256] = 0.f; g_sumsq[threadIdx.x + 256] = 0.f;
    }
    if (bx < NXB) {
        int p = bx * 256 + threadIdx.x;
        float2 v = ((const float2*)x)[p];
        u32 lw, hw = pack_hi2(v.x, v.y, lw);
        ((u32*)g_hs_hi)[p] = hw;
        ((u32*)g_hs_lo)[p] = lw;
    } else {
        int i = (bx - NXB) * 256 + threadIdx.x;
        bf16 h, l;
        split2(w1[i], h, l);
        g_w1s_hi[i] = h;
        g_w1s_lo[i] = l;
    }
}

// ============================================================================
// Host driver — graph-capturable: 25 kernel launches, no sync, no allocs.
// ============================================================================
extern "C" void kernel_launch(void* const* d_in, const int* in_sizes, int n_in,
                              void* d_out, int out_size)
{
    const float* x   = (const float*)d_in[0];
    const float* w1  = (const float*)d_in[1];
    const float* b1  = (const float*)d_in[2];
    const float* a1  = (const float*)d_in[3];
    const float* g1  = (const float*)d_in[4];
    const float* be1 = (const float*)d_in[5];
    const float* wd  = (const float*)d_in[6];
    const float* bd  = (const float*)d_in[7];
    const float* a2  = (const float*)d_in[8];
    const float* g2  = (const float*)d_in[9];
    const float* be2 = (const float*)d_in[10];
    const float* w2  = (const float*)d_in[11];
    const float* b2  = (const float*)d_in[12];
    float* out = (float*)d_out;

    prep_kernel<<<NXB + NWB, 256>>>(x, w1);                           // #1

    dim3 gg1(125, 4, 8);   // t-tiles, m-tiles (512/128), batch
    dim3 gg2(125, 1, 8);   // t-tiles, m-tiles (128/128), batch
    dim3 gdw(8, 512, 8);

    for (int l = 0; l < Ll; l++) {
        gemm_tc_kernel<<<gg1, 256>>>(0, 0, l, b1 + l * Dd, a1 + l,
                                     x, nullptr);                     // #2 (l=0)
        finalize1_kernel<<<1, 512>>>(g1 + l * Dd, be1 + l * Dd);      // #3 (l=0)
        dw_kernel<<<gdw, 256>>>(wd + l * Dd * 3, bd + l * Dd,
                                a2 + l, 1 << l);                      // #4 = profiled
        finalize2a_kernel<<<1, 512>>>(g2 + l * Dd, be2 + l * Dd);
        convert_w2_kernel<<<128, 256>>>(w2 + l * Cc * Dd, b2 + l * Cc);
        gemm_tc_kernel<<<gg2, 256>>>(1, l == Ll - 1 ? 1 : 0, l,
                                     nullptr, nullptr, x, out);
    }
}